// round 12
// baseline (speedup 1.0000x reference)
#include <cuda_runtime.h>
#include <cuda_bf16.h>
#include <mma.h>
#include <cstdint>

using namespace nvcuda;

// Problem constants (fixed shapes from reference)
#define B_    16
#define N_    256
#define EDIM  1024
#define F_    2
#define C_    512          // EDIM / F_
#define NE    4096         // codebook size
#define NTOK  8192         // B_*F_*N_
#define BN    4096         // B_*N_ tokens per codebook
#define ZQ_ELEMS 4194304   // B_*N_*EDIM
#define EPS_  1e-12f
#define MARGIN 0.06f       // > worst-case (bf16 gemm + bf16 storage) error in d-space
#define NTILES 16          // NE / 256 column tiles per codebook

// ---- device scratch (static: no runtime allocations) ----
__device__ float g_invp[NTOK];                 // 1/max(||emb_row||,eps)
__device__ float g_nrmz[NTOK];                 // max(||zf_token||,eps)
__device__ float g_loss_part[NTOK];
__device__ unsigned g_tmin[NTOK * NTILES];     // ord-encoded min d per (token, col-tile)
__device__ __nv_bfloat16 g_zbf[NTOK * C_];     // normalized z in bf16  [f][bn][c]
__device__ __nv_bfloat16 g_pbf[NTOK * C_];     // normalized protos bf16 [f][n][c]
__device__ __nv_bfloat16 g_sbf[(size_t)NTOK * NE];  // approx cos matrix bf16 (64MB)

// float -> order-preserving uint32 (and back)
__device__ __forceinline__ unsigned f2ord(float f) {
    unsigned u = __float_as_uint(f);
    return (u & 0x80000000u) ? ~u : (u | 0x80000000u);
}
__device__ __forceinline__ float ord2f(unsigned o) {
    unsigned u = (o & 0x80000000u) ? (o & 0x7FFFFFFFu) : ~o;
    return __uint_as_float(u);
}
__device__ __forceinline__ uint32_t smem_u32(const void* p) {
    uint32_t a;
    asm("{ .reg .u64 t; cvta.to.shared.u64 t, %1; cvt.u32.u64 %0, t; }" : "=r"(a) : "l"(p));
    return a;
}
#define CP_ASYNC16(smem, gptr) \
    asm volatile("cp.async.cg.shared.global [%0], [%1], 16;" :: "r"(smem), "l"(gptr) : "memory")
#define CP_COMMIT() asm volatile("cp.async.commit_group;" ::: "memory")
#define CP_WAIT(n)  asm volatile("cp.async.wait_group %0;" :: "n"(n) : "memory")

// ---------------------------------------------------------------------------
// 1) fused norms + bf16 convert. One 128-thread block per row.
//    rows [0,8192): emb rows -> g_invp, g_pbf ; rows [8192,16384): tokens -> g_nrmz, g_zbf
// ---------------------------------------------------------------------------
__global__ __launch_bounds__(128)
void normconv_kernel(const float* __restrict__ z, const float* __restrict__ emb) {
    const int rid = blockIdx.x;
    const int tid = threadIdx.x;
    const bool is_emb = rid < NTOK;

    const float* src;
    __nv_bfloat16* dst;
    if (is_emb) {
        src = emb + (size_t)rid * C_;
        dst = g_pbf + (size_t)rid * C_;
    } else {
        int t  = rid - NTOK;
        int f  = t >> 12;
        int bn = t & (BN - 1);
        src = z + (size_t)bn * EDIM + f * C_;
        dst = g_zbf + (size_t)t * C_;
    }

    float4 v = *reinterpret_cast<const float4*>(src + tid * 4);
    float s = v.x * v.x + v.y * v.y + v.z * v.z + v.w * v.w;
    #pragma unroll
    for (int o = 16; o > 0; o >>= 1) s += __shfl_xor_sync(0xFFFFFFFFu, s, o);
    __shared__ float sw[4];
    __shared__ float inv_s;
    int lane = tid & 31, wid = tid >> 5;
    if (lane == 0) sw[wid] = s;
    __syncthreads();
    if (tid == 0) {
        float tot = (sw[0] + sw[1]) + (sw[2] + sw[3]);
        float nrm = fmaxf(sqrtf(tot), EPS_);
        float inv = 1.0f / nrm;
        inv_s = inv;
        if (is_emb) g_invp[rid] = inv;
        else        g_nrmz[rid - NTOK] = nrm;
    }
    __syncthreads();
    float inv = inv_s;
    __nv_bfloat162 lo = __floats2bfloat162_rn(v.x * inv, v.y * inv);
    __nv_bfloat162 hi = __floats2bfloat162_rn(v.z * inv, v.w * inv);
    uint2 pk;
    pk.x = *reinterpret_cast<uint32_t*>(&lo);
    pk.y = *reinterpret_cast<uint32_t*>(&hi);
    *reinterpret_cast<uint2*>(dst + tid * 4) = pk;
}

// ---------------------------------------------------------------------------
// 2) WMMA GEMM: CTA = 128 tokens x 256 protos, 8 warps each 64x64 (4x4 frags).
//    K=512 in 16 chunks of 32, cp.async 3-stage pipeline.
//    LDPAD=40 halves (80B stride) -> conflict-free ldmatrix phases.
//    Epilogue: s -> bf16 g_sbf, per-(row, col-tile) min d -> g_tmin (plain store).
// ---------------------------------------------------------------------------
#define LDPAD 40                         // padded shared row in halves (80 B, conflict-free)
#define A_BYTES (128 * LDPAD * 2)        // 10240
#define B_BYTES (256 * LDPAD * 2)        // 20480
#define BUF_BYTES (A_BYTES + B_BYTES)    // 30720
#define NSTAGE 3
#define SMEM_DYN (NSTAGE * BUF_BYTES)    // 92160

__global__ __launch_bounds__(256)
void wmma_gemm_kernel() {
    extern __shared__ char smem[];
    const uint32_t sb = smem_u32(smem);

    const int tid  = threadIdx.x;
    const int warp = tid >> 5;
    const int lane = tid & 31;
    const int wm = warp >> 2;            // 0..1 : 64-row slab
    const int wn = warp & 3;             // 0..3 : 64-col slab
    const int f  = blockIdx.z;
    const int m0 = blockIdx.y * 128;
    const int n0 = blockIdx.x * 256;

    const __nv_bfloat16* Abase = g_zbf + (size_t)(f * BN + m0) * C_;
    const __nv_bfloat16* Bbase = g_pbf + (size_t)(f * NE + n0) * C_;

    auto load_chunk = [&](int c, int buf) {
        uint32_t abuf = sb + buf * BUF_BYTES;
        uint32_t bbuf = abuf + A_BYTES;
        #pragma unroll
        for (int j = 0; j < 2; ++j) {
            int idx = tid + j * 256;               // 0..511
            int row = idx >> 2, seg = idx & 3;
            CP_ASYNC16(abuf + row * (LDPAD * 2) + seg * 16,
                       Abase + (size_t)row * C_ + c * 32 + seg * 8);
        }
        #pragma unroll
        for (int j = 0; j < 4; ++j) {
            int idx = tid + j * 256;               // 0..1023
            int row = idx >> 2, seg = idx & 3;
            CP_ASYNC16(bbuf + row * (LDPAD * 2) + seg * 16,
                       Bbase + (size_t)row * C_ + c * 32 + seg * 8);
        }
    };

    wmma::fragment<wmma::accumulator, 16, 16, 16, float> acc[4][4];
    #pragma unroll
    for (int i = 0; i < 4; i++)
        #pragma unroll
        for (int j = 0; j < 4; j++) wmma::fill_fragment(acc[i][j], 0.0f);

    load_chunk(0, 0); CP_COMMIT();
    load_chunk(1, 1); CP_COMMIT();

    int buf = 0;
    for (int c = 0; c < 16; ++c) {
        if (c + 2 < 16) {
            load_chunk(c + 2, (c + 2) % NSTAGE);
            CP_COMMIT();
            CP_WAIT(2);
        } else if (c + 1 < 16) {
            CP_WAIT(1);
        } else {
            CP_WAIT(0);
        }
        __syncthreads();

        const __nv_bfloat16* As = reinterpret_cast<const __nv_bfloat16*>(smem + buf * BUF_BYTES);
        const __nv_bfloat16* Bs = reinterpret_cast<const __nv_bfloat16*>(smem + buf * BUF_BYTES + A_BYTES);
        #pragma unroll
        for (int kk = 0; kk < 32; kk += 16) {
            wmma::fragment<wmma::matrix_a, 16, 16, 16, __nv_bfloat16, wmma::row_major> af[4];
            #pragma unroll
            for (int i = 0; i < 4; i++)
                wmma::load_matrix_sync(af[i], As + (wm * 64 + i * 16) * LDPAD + kk, LDPAD);
            #pragma unroll
            for (int j = 0; j < 4; j++) {
                wmma::fragment<wmma::matrix_b, 16, 16, 16, __nv_bfloat16, wmma::col_major> bf;
                wmma::load_matrix_sync(bf, Bs + (wn * 64 + j * 16) * LDPAD + kk, LDPAD);
                #pragma unroll
                for (int i = 0; i < 4; i++)
                    wmma::mma_sync(acc[i][j], af[i], bf, acc[i][j]);
            }
        }
        __syncthreads();
        buf = (buf + 1) % NSTAGE;
    }

    // epilogue: per-warp staging; write bf16 s; 4-warp smem reduce -> g_tmin plain store
    float* stage = reinterpret_cast<float*>(smem) + warp * 256;           // 8KB
    float* rowmax = reinterpret_cast<float*>(smem) + 8 * 256 + 0;         // [128][4]
    const int r = lane >> 1, h = lane & 1;      // row 0..15, col half 0..1
    #pragma unroll
    for (int i = 0; i < 4; ++i) {
        const int lrow = wm * 64 + i * 16 + r;                 // 0..127 within CTA
        const int trow = f * BN + m0 + lrow;                   // token id
        float smax = -1e30f;
        #pragma unroll
        for (int j = 0; j < 4; ++j) {
            wmma::store_matrix_sync(stage, acc[i][j], 16, wmma::mem_row_major);
            __syncwarp();
            float v[8];
            #pragma unroll
            for (int e = 0; e < 8; ++e) v[e] = stage[r * 16 + h * 8 + e];
            uint32_t* dst = reinterpret_cast<uint32_t*>(
                g_sbf + (size_t)trow * NE + n0 + wn * 64 + j * 16 + h * 8);
            #pragma unroll
            for (int p = 0; p < 4; ++p) {
                __nv_bfloat162 p2 = __floats2bfloat162_rn(v[2 * p], v[2 * p + 1]);
                dst[p] = *reinterpret_cast<uint32_t*>(&p2);
                smax = fmaxf(smax, fmaxf(v[2 * p], v[2 * p + 1]));
            }
            __syncwarp();
        }
        smax = fmaxf(smax, __shfl_xor_sync(0xFFFFFFFFu, smax, 1));
        if (h == 0) rowmax[lrow * 4 + wn] = smax;
    }
    __syncthreads();
    if (tid < 128) {
        float s4 = fmaxf(fmaxf(rowmax[tid * 4 + 0], rowmax[tid * 4 + 1]),
                         fmaxf(rowmax[tid * 4 + 2], rowmax[tid * 4 + 3]));
        float d = __fsub_rn(2.0f, __fmul_rn(2.0f, s4));
        g_tmin[(f * BN + m0 + tid) * NTILES + blockIdx.x] = f2ord(d);
    }
}

// ---------------------------------------------------------------------------
// 3) select + gather fused: tile-min pruning, bf16 candidate scan, exact fp32
//    rescore, then straight-through output + loss partial. One block per token.
// ---------------------------------------------------------------------------
__global__ __launch_bounds__(256)
void select_gather_kernel(const float* __restrict__ z, const float* __restrict__ emb,
                          float* __restrict__ out, int out_size) {
    const int t  = blockIdx.x;
    const int f  = t >> 12;
    const int bn = t & (BN - 1);
    const int b  = bn >> 8;
    const int n  = bn & 255;
    const int tid = threadIdx.x;

    __shared__ float thr_s;
    __shared__ int cand[512];
    __shared__ int cnt;
    __shared__ unsigned long long bestk;
    __shared__ float ztok[C_];

    if (tid < 32) {
        float v = (tid < NTILES) ? ord2f(g_tmin[t * NTILES + tid]) : 1e30f;
        #pragma unroll
        for (int o = 16; o > 0; o >>= 1) v = fminf(v, __shfl_xor_sync(0xFFFFFFFFu, v, o));
        if (tid == 0) { thr_s = v + MARGIN; cnt = 0; bestk = 0ull; }
    }
    for (int i = tid; i < C_; i += 256)
        ztok[i] = z[(size_t)bn * EDIM + f * C_ + i];
    __syncthreads();
    const float thr = thr_s;

    for (int tile = 0; tile < NTILES; ++tile) {
        if (ord2f(g_tmin[t * NTILES + tile]) > thr) continue;
        float s = __bfloat162float(g_sbf[(size_t)t * NE + tile * 256 + tid]);
        float d = __fsub_rn(2.0f, __fmul_rn(2.0f, s));
        if (d <= thr) {
            int p = atomicAdd(&cnt, 1);
            if (p < 512) cand[p] = tile * 256 + tid;
        }
    }
    __syncthreads();

    const float nz = g_nrmz[t];
    const float invz = 1.0f / nz;
    const int nc = min(cnt, 512);
    const int warp = tid >> 5, lane = tid & 31;

    for (int c = warp; c < nc; c += 8) {
        int j = cand[c];
        const float* er = emb + (size_t)(f * NE + j) * C_;
        float s = 0.f;
        for (int i = lane; i < C_; i += 32) s += ztok[i] * er[i];
        #pragma unroll
        for (int o = 16; o > 0; o >>= 1) s += __shfl_xor_sync(0xFFFFFFFFu, s, o);
        if (lane == 0) {
            s = s * g_invp[f * NE + j] * invz;
            float d = __fsub_rn(2.0f, __fmul_rn(2.0f, s));
            unsigned long long key =
                ((unsigned long long)(~f2ord(d)) << 32) | (0xFFFFFFFFu - (unsigned)j);
            atomicMax(&bestk, key);
        }
    }
    __syncthreads();

    const unsigned m = 0xFFFFFFFFu - (unsigned)(bestk & 0xFFFFFFFFull);
    const float qscale = g_invp[m];

    // gather: 2 elements per thread, exact reference rounding
    int j = tid * 2;
    float2 vq = *reinterpret_cast<const float2*>(emb + (size_t)m * C_ + j);
    float qv[2] = {vq.x, vq.y};
    float zv[2] = {ztok[j], ztok[j + 1]};
    float o[2], lsum = 0.f;
    #pragma unroll
    for (int q = 0; q < 2; q++) {
        float zq = __fmul_rn(qv[q], qscale);
        float zn = __fdiv_rn(zv[q], nz);
        float dd = __fsub_rn(zq, zn);
        o[q] = __fadd_rn(zn, dd);
        lsum += dd * dd;
    }
    int obase = bn * EDIM + f * C_ + j;
    if (obase + 1 < out_size) {
        float2 ov; ov.x = o[0]; ov.y = o[1];
        *reinterpret_cast<float2*>(out + obase) = ov;
    }

    #pragma unroll
    for (int ofs = 16; ofs > 0; ofs >>= 1) lsum += __shfl_xor_sync(0xFFFFFFFFu, lsum, ofs);
    __shared__ float sw[8];
    if (lane == 0) sw[warp] = lsum;
    __syncthreads();
    if (tid == 0) {
        float tot = ((sw[0] + sw[1]) + (sw[2] + sw[3])) + ((sw[4] + sw[5]) + (sw[6] + sw[7]));
        g_loss_part[t] = tot;
        int p = ZQ_ELEMS + 1 + ((b * 2 + f) << 8) + n;
        if (p < out_size) out[p] = (float)m;
    }
}

// ---------------------------------------------------------------------------
// 4) final loss: deterministic fixed-order reduction of 8192 partials.
// ---------------------------------------------------------------------------
__global__ void loss_kernel(float* __restrict__ out, int out_size) {
    __shared__ float sh[256];
    float s = 0.f;
    for (int i = threadIdx.x; i < NTOK; i += 256) s += g_loss_part[i];
    sh[threadIdx.x] = s;
    __syncthreads();
    for (int st = 128; st > 0; st >>= 1) {
        if (threadIdx.x < st) sh[threadIdx.x] += sh[threadIdx.x + st];
        __syncthreads();
    }
    if (threadIdx.x == 0 && out_size > ZQ_ELEMS) {
        float mean = sh[0] / (float)ZQ_ELEMS;
        out[ZQ_ELEMS] = __fadd_rn(__fmul_rn(0.25f, mean), mean);
    }
}

// ---------------------------------------------------------------------------
extern "C" void kernel_launch(void* const* d_in, const int* in_sizes, int n_in,
                              void* d_out, int out_size) {
    const float* z   = (const float*)d_in[0];
    const float* emb = (const float*)d_in[1];
    float* out = (float*)d_out;
    (void)in_sizes; (void)n_in;

    cudaFuncSetAttribute(wmma_gemm_kernel, cudaFuncAttributeMaxDynamicSharedMemorySize, SMEM_DYN);

    normconv_kernel<<<2 * NTOK, 128>>>(z, emb);
    wmma_gemm_kernel<<<dim3(NE / 256, BN / 128, F_), 256, SMEM_DYN>>>();
    select_gather_kernel<<<NTOK, 256>>>(z, emb, out, out_size);
    loss_kernel<<<1, 256>>>(out, out_size);
}

// round 13
// speedup vs baseline: 1.3487x; 1.3487x over previous
#include <cuda_runtime.h>
#include <cuda_fp16.h>
#include <mma.h>
#include <cstdint>

using namespace nvcuda;

// Problem constants (fixed shapes from reference)
#define B_    16
#define N_    256
#define EDIM  1024
#define F_    2
#define C_    512          // EDIM / F_
#define NE    4096         // codebook size
#define NTOK  8192         // B_*F_*N_
#define BN    4096         // B_*N_ tokens per codebook
#define ZQ_ELEMS 4194304   // B_*N_*EDIM
#define EPS_  1e-12f
#define MARGIN 0.06f       // >> worst-case (fp16 gemm + f16 acc + fp16 storage) error in d-space
#define NTILES 16          // NE / 256 column tiles per codebook

// ---- device scratch (static: no runtime allocations) ----
__device__ float g_invp[NTOK];                 // 1/max(||emb_row||,eps)
__device__ float g_nrmz[NTOK];                 // max(||zf_token||,eps)
__device__ float g_loss_part[NTOK];
__device__ unsigned g_tmin[NTOK * NTILES];     // ord-encoded min d per (token, col-tile)
__device__ __half g_zhf[NTOK * C_];            // normalized z in fp16  [f][bn][c]
__device__ __half g_phf[NTOK * C_];            // normalized protos fp16 [f][n][c]
__device__ __half g_shf[(size_t)NTOK * NE];    // approx cos matrix fp16 (64MB)

// float -> order-preserving uint32 (and back)
__device__ __forceinline__ unsigned f2ord(float f) {
    unsigned u = __float_as_uint(f);
    return (u & 0x80000000u) ? ~u : (u | 0x80000000u);
}
__device__ __forceinline__ float ord2f(unsigned o) {
    unsigned u = (o & 0x80000000u) ? (o & 0x7FFFFFFFu) : ~o;
    return __uint_as_float(u);
}
__device__ __forceinline__ uint32_t smem_u32(const void* p) {
    uint32_t a;
    asm("{ .reg .u64 t; cvta.to.shared.u64 t, %1; cvt.u32.u64 %0, t; }" : "=r"(a) : "l"(p));
    return a;
}
#define CP_ASYNC16(smem, gptr) \
    asm volatile("cp.async.cg.shared.global [%0], [%1], 16;" :: "r"(smem), "l"(gptr) : "memory")
#define CP_COMMIT() asm volatile("cp.async.commit_group;" ::: "memory")
#define CP_WAIT(n)  asm volatile("cp.async.wait_group %0;" :: "n"(n) : "memory")

// ---------------------------------------------------------------------------
// 1) fused norms + fp16 convert. One 128-thread block per row.
//    rows [0,8192): emb rows -> g_invp, g_phf ; rows [8192,16384): tokens -> g_nrmz, g_zhf
// ---------------------------------------------------------------------------
__global__ __launch_bounds__(128)
void normconv_kernel(const float* __restrict__ z, const float* __restrict__ emb) {
    const int rid = blockIdx.x;
    const int tid = threadIdx.x;
    const bool is_emb = rid < NTOK;

    const float* src;
    __half* dst;
    if (is_emb) {
        src = emb + (size_t)rid * C_;
        dst = g_phf + (size_t)rid * C_;
    } else {
        int t  = rid - NTOK;
        int f  = t >> 12;
        int bn = t & (BN - 1);
        src = z + (size_t)bn * EDIM + f * C_;
        dst = g_zhf + (size_t)t * C_;
    }

    float4 v = *reinterpret_cast<const float4*>(src + tid * 4);
    float s = v.x * v.x + v.y * v.y + v.z * v.z + v.w * v.w;
    #pragma unroll
    for (int o = 16; o > 0; o >>= 1) s += __shfl_xor_sync(0xFFFFFFFFu, s, o);
    __shared__ float sw[4];
    __shared__ float inv_s;
    int lane = tid & 31, wid = tid >> 5;
    if (lane == 0) sw[wid] = s;
    __syncthreads();
    if (tid == 0) {
        float tot = (sw[0] + sw[1]) + (sw[2] + sw[3]);
        float nrm = fmaxf(sqrtf(tot), EPS_);
        float inv = 1.0f / nrm;
        inv_s = inv;
        if (is_emb) g_invp[rid] = inv;
        else        g_nrmz[rid - NTOK] = nrm;
    }
    __syncthreads();
    float inv = inv_s;
    __half2 lo = __floats2half2_rn(v.x * inv, v.y * inv);
    __half2 hi = __floats2half2_rn(v.z * inv, v.w * inv);
    uint2 pk;
    pk.x = *reinterpret_cast<uint32_t*>(&lo);
    pk.y = *reinterpret_cast<uint32_t*>(&hi);
    *reinterpret_cast<uint2*>(dst + tid * 4) = pk;
}

// ---------------------------------------------------------------------------
// 2) WMMA GEMM (fp16 in, f16 acc): CTA = 128 tokens x 256 protos, 8 warps each
//    64x64 (4x4 frags). K=512 in 16 chunks of 32, cp.async 3-stage pipeline.
//    Epilogue: s -> fp16 g_shf, per-(row, col-tile) min d -> g_tmin (plain store).
// ---------------------------------------------------------------------------
#define LDPAD 40                         // padded shared row in halves (80 B, conflict-free)
#define A_BYTES (128 * LDPAD * 2)        // 10240
#define B_BYTES (256 * LDPAD * 2)        // 20480
#define BUF_BYTES (A_BYTES + B_BYTES)    // 30720
#define NSTAGE 3
#define SMEM_DYN (NSTAGE * BUF_BYTES)    // 92160

__global__ __launch_bounds__(256)
void wmma_gemm_kernel() {
    extern __shared__ char smem[];
    const uint32_t sb = smem_u32(smem);

    const int tid  = threadIdx.x;
    const int warp = tid >> 5;
    const int lane = tid & 31;
    const int wm = warp >> 2;            // 0..1 : 64-row slab
    const int wn = warp & 3;             // 0..3 : 64-col slab
    const int f  = blockIdx.z;
    const int m0 = blockIdx.y * 128;
    const int n0 = blockIdx.x * 256;

    const __half* Abase = g_zhf + (size_t)(f * BN + m0) * C_;
    const __half* Bbase = g_phf + (size_t)(f * NE + n0) * C_;

    auto load_chunk = [&](int c, int buf) {
        uint32_t abuf = sb + buf * BUF_BYTES;
        uint32_t bbuf = abuf + A_BYTES;
        #pragma unroll
        for (int j = 0; j < 2; ++j) {
            int idx = tid + j * 256;               // 0..511
            int row = idx >> 2, seg = idx & 3;
            CP_ASYNC16(abuf + row * (LDPAD * 2) + seg * 16,
                       Abase + (size_t)row * C_ + c * 32 + seg * 8);
        }
        #pragma unroll
        for (int j = 0; j < 4; ++j) {
            int idx = tid + j * 256;               // 0..1023
            int row = idx >> 2, seg = idx & 3;
            CP_ASYNC16(bbuf + row * (LDPAD * 2) + seg * 16,
                       Bbase + (size_t)row * C_ + c * 32 + seg * 8);
        }
    };

    wmma::fragment<wmma::accumulator, 16, 16, 16, __half> acc[4][4];
    #pragma unroll
    for (int i = 0; i < 4; i++)
        #pragma unroll
        for (int j = 0; j < 4; j++) wmma::fill_fragment(acc[i][j], __float2half(0.0f));

    load_chunk(0, 0); CP_COMMIT();
    load_chunk(1, 1); CP_COMMIT();

    int buf = 0;
    for (int c = 0; c < 16; ++c) {
        if (c + 2 < 16) {
            load_chunk(c + 2, (c + 2) % NSTAGE);
            CP_COMMIT();
            CP_WAIT(2);
        } else if (c + 1 < 16) {
            CP_WAIT(1);
        } else {
            CP_WAIT(0);
        }
        __syncthreads();

        const __half* As = reinterpret_cast<const __half*>(smem + buf * BUF_BYTES);
        const __half* Bs = reinterpret_cast<const __half*>(smem + buf * BUF_BYTES + A_BYTES);
        #pragma unroll
        for (int kk = 0; kk < 32; kk += 16) {
            wmma::fragment<wmma::matrix_a, 16, 16, 16, __half, wmma::row_major> af[4];
            #pragma unroll
            for (int i = 0; i < 4; i++)
                wmma::load_matrix_sync(af[i], As + (wm * 64 + i * 16) * LDPAD + kk, LDPAD);
            #pragma unroll
            for (int j = 0; j < 4; j++) {
                wmma::fragment<wmma::matrix_b, 16, 16, 16, __half, wmma::col_major> bf;
                wmma::load_matrix_sync(bf, Bs + (wn * 64 + j * 16) * LDPAD + kk, LDPAD);
                #pragma unroll
                for (int i = 0; i < 4; i++)
                    wmma::mma_sync(acc[i][j], af[i], bf, acc[i][j]);
            }
        }
        __syncthreads();
        buf = (buf + 1) % NSTAGE;
    }

    // epilogue: per-warp half staging; write fp16 s; 4-warp smem reduce -> g_tmin
    __half* stage = reinterpret_cast<__half*>(smem) + warp * 256;         // 512B per warp
    float* rowmax = reinterpret_cast<float*>(smem + 8 * 512);             // [128][4]
    const int r = lane >> 1, h = lane & 1;      // row 0..15, col half 0..1
    #pragma unroll
    for (int i = 0; i < 4; ++i) {
        const int lrow = wm * 64 + i * 16 + r;                 // 0..127 within CTA
        const int trow = f * BN + m0 + lrow;                   // token id
        float smax = -1e30f;
        #pragma unroll
        for (int j = 0; j < 4; ++j) {
            wmma::store_matrix_sync(stage, acc[i][j], 16, wmma::mem_row_major);
            __syncwarp();
            uint4 pk = *reinterpret_cast<const uint4*>(stage + r * 16 + h * 8);
            const __half2* hp = reinterpret_cast<const __half2*>(&pk);
            #pragma unroll
            for (int p = 0; p < 4; ++p) {
                float2 fv = __half22float2(hp[p]);
                smax = fmaxf(smax, fmaxf(fv.x, fv.y));
            }
            *reinterpret_cast<uint4*>(
                g_shf + (size_t)trow * NE + n0 + wn * 64 + j * 16 + h * 8) = pk;
            __syncwarp();
        }
        smax = fmaxf(smax, __shfl_xor_sync(0xFFFFFFFFu, smax, 1));
        if (h == 0) rowmax[lrow * 4 + wn] = smax;
    }
    __syncthreads();
    if (tid < 128) {
        float s4 = fmaxf(fmaxf(rowmax[tid * 4 + 0], rowmax[tid * 4 + 1]),
                         fmaxf(rowmax[tid * 4 + 2], rowmax[tid * 4 + 3]));
        float d = __fsub_rn(2.0f, __fmul_rn(2.0f, s4));
        g_tmin[(f * BN + m0 + tid) * NTILES + blockIdx.x] = f2ord(d);
    }
}

// ---------------------------------------------------------------------------
// 3) select + gather fused: tile-min pruning, fp16 candidate scan, exact fp32
//    rescore, then straight-through output + loss partial. One block per token.
// ---------------------------------------------------------------------------
__global__ __launch_bounds__(256)
void select_gather_kernel(const float* __restrict__ z, const float* __restrict__ emb,
                          float* __restrict__ out, int out_size) {
    const int t  = blockIdx.x;
    const int f  = t >> 12;
    const int bn = t & (BN - 1);
    const int b  = bn >> 8;
    const int n  = bn & 255;
    const int tid = threadIdx.x;

    __shared__ float thr_s;
    __shared__ int cand[512];
    __shared__ int cnt;
    __shared__ unsigned long long bestk;
    __shared__ float ztok[C_];

    if (tid < 32) {
        float v = (tid < NTILES) ? ord2f(g_tmin[t * NTILES + tid]) : 1e30f;
        #pragma unroll
        for (int o = 16; o > 0; o >>= 1) v = fminf(v, __shfl_xor_sync(0xFFFFFFFFu, v, o));
        if (tid == 0) { thr_s = v + MARGIN; cnt = 0; bestk = 0ull; }
    }
    for (int i = tid; i < C_; i += 256)
        ztok[i] = z[(size_t)bn * EDIM + f * C_ + i];
    __syncthreads();
    const float thr = thr_s;

    for (int tile = 0; tile < NTILES; ++tile) {
        if (ord2f(g_tmin[t * NTILES + tile]) > thr) continue;
        float s = __half2float(g_shf[(size_t)t * NE + tile * 256 + tid]);
        float d = __fsub_rn(2.0f, __fmul_rn(2.0f, s));
        if (d <= thr) {
            int p = atomicAdd(&cnt, 1);
            if (p < 512) cand[p] = tile * 256 + tid;
        }
    }
    __syncthreads();

    const float nz = g_nrmz[t];
    const float invz = 1.0f / nz;
    const int nc = min(cnt, 512);
    const int warp = tid >> 5, lane = tid & 31;

    for (int c = warp; c < nc; c += 8) {
        int j = cand[c];
        const float* er = emb + (size_t)(f * NE + j) * C_;
        float s = 0.f;
        for (int i = lane; i < C_; i += 32) s += ztok[i] * er[i];
        #pragma unroll
        for (int o = 16; o > 0; o >>= 1) s += __shfl_xor_sync(0xFFFFFFFFu, s, o);
        if (lane == 0) {
            s = s * g_invp[f * NE + j] * invz;
            float d = __fsub_rn(2.0f, __fmul_rn(2.0f, s));
            unsigned long long key =
                ((unsigned long long)(~f2ord(d)) << 32) | (0xFFFFFFFFu - (unsigned)j);
            atomicMax(&bestk, key);
        }
    }
    __syncthreads();

    const unsigned m = 0xFFFFFFFFu - (unsigned)(bestk & 0xFFFFFFFFull);
    const float qscale = g_invp[m];

    // gather: 2 elements per thread, exact reference rounding
    int j = tid * 2;
    float2 vq = *reinterpret_cast<const float2*>(emb + (size_t)m * C_ + j);
    float qv[2] = {vq.x, vq.y};
    float zv[2] = {ztok[j], ztok[j + 1]};
    float o[2], lsum = 0.f;
    #pragma unroll
    for (int q = 0; q < 2; q++) {
        float zq = __fmul_rn(qv[q], qscale);
        float zn = __fdiv_rn(zv[q], nz);
        float dd = __fsub_rn(zq, zn);
        o[q] = __fadd_rn(zn, dd);
        lsum += dd * dd;
    }
    int obase = bn * EDIM + f * C_ + j;
    if (obase + 1 < out_size) {
        float2 ov; ov.x = o[0]; ov.y = o[1];
        *reinterpret_cast<float2*>(out + obase) = ov;
    }

    #pragma unroll
    for (int ofs = 16; ofs > 0; ofs >>= 1) lsum += __shfl_xor_sync(0xFFFFFFFFu, lsum, ofs);
    __shared__ float sw[8];
    if (lane == 0) sw[warp] = lsum;
    __syncthreads();
    if (tid == 0) {
        float tot = ((sw[0] + sw[1]) + (sw[2] + sw[3])) + ((sw[4] + sw[5]) + (sw[6] + sw[7]));
        g_loss_part[t] = tot;
        int p = ZQ_ELEMS + 1 + ((b * 2 + f) << 8) + n;
        if (p < out_size) out[p] = (float)m;
    }
}

// ---------------------------------------------------------------------------
// 4) final loss: deterministic fixed-order reduction of 8192 partials.
// ---------------------------------------------------------------------------
__global__ void loss_kernel(float* __restrict__ out, int out_size) {
    __shared__ float sh[256];
    float s = 0.f;
    for (int i = threadIdx.x; i < NTOK; i += 256) s += g_loss_part[i];
    sh[threadIdx.x] = s;
    __syncthreads();
    for (int st = 128; st > 0; st >>= 1) {
        if (threadIdx.x < st) sh[threadIdx.x] += sh[threadIdx.x + st];
        __syncthreads();
    }
    if (threadIdx.x == 0 && out_size > ZQ_ELEMS) {
        float mean = sh[0] / (float)ZQ_ELEMS;
        out[ZQ_ELEMS] = __fadd_rn(__fmul_rn(0.25f, mean), mean);
    }
}

// ---------------------------------------------------------------------------
extern "C" void kernel_launch(void* const* d_in, const int* in_sizes, int n_in,
                              void* d_out, int out_size) {
    const float* z   = (const float*)d_in[0];
    const float* emb = (const float*)d_in[1];
    float* out = (float*)d_out;
    (void)in_sizes; (void)n_in;

    cudaFuncSetAttribute(wmma_gemm_kernel, cudaFuncAttributeMaxDynamicSharedMemorySize, SMEM_DYN);

    normconv_kernel<<<2 * NTOK, 128>>>(z, emb);
    wmma_gemm_kernel<<<dim3(NE / 256, BN / 128, F_), 256, SMEM_DYN>>>();
    select_gather_kernel<<<NTOK, 256>>>(z, emb, out, out_size);
    loss_kernel<<<1, 256>>>(out, out_size);
}